// round 1
// baseline (speedup 1.0000x reference)
#include <cuda_runtime.h>
#include <math.h>

#define SEQ   2048
#define BATCH 2
#define NH    16
#define HD    64
#define DM    1024
#define WIN   256

// Scratch (device globals: the allocation-guard-legal path)
__device__ float g_Q[(size_t)BATCH * NH * SEQ * HD];
__device__ float g_K[(size_t)BATCH * NH * SEQ * HD];
__device__ float g_V[(size_t)BATCH * NH * SEQ * HD];
__device__ float g_C[(size_t)BATCH * SEQ * DM];

// ---------------------------------------------------------------------------
// SGEMM building block: 128x128 block tile, K-tile 16, 256 threads, 8x8 micro
// ---------------------------------------------------------------------------

// QKV projection: A = x [4096,1024], B = W{q,k,v} [1024,1024]
// Output scattered into [b,h,s,hd] layout.
__global__ __launch_bounds__(256) void qkv_gemm_kernel(
    const float* __restrict__ x,
    const float* __restrict__ Wq,
    const float* __restrict__ Wk,
    const float* __restrict__ Wv)
{
    const int bn = blockIdx.x;      // 0..7   (N/128)
    const int bm = blockIdx.y;      // 0..31  (M/128)
    const int w  = blockIdx.z;      // 0..2

    const float* __restrict__ Bw = (w == 0) ? Wq : ((w == 1) ? Wk : Wv);
    float* __restrict__ Out      = (w == 0) ? g_Q : ((w == 1) ? g_K : g_V);

    __shared__ float As[16][132];   // transposed A tile, padded
    __shared__ float Bs[16][132];

    const int tid = threadIdx.x;
    const int tx = tid & 15;        // 0..15 (col group)
    const int ty = tid >> 4;        // 0..15 (row group)

    const int row0 = bm * 128;
    const int col0 = bn * 128;

    float acc[8][8];
#pragma unroll
    for (int i = 0; i < 8; i++)
#pragma unroll
        for (int j = 0; j < 8; j++) acc[i][j] = 0.f;

    for (int k0 = 0; k0 < DM; k0 += 16) {
        // Load A tile: 128 rows x 16 cols = 512 float4
#pragma unroll
        for (int it = 0; it < 2; it++) {
            int idx = tid + it * 256;            // float4 idx
            int r   = idx >> 2;                  // 0..127
            int c4  = idx & 3;                   // 0..3
            float4 v = *(const float4*)(x + (size_t)(row0 + r) * DM + k0 + c4 * 4);
            As[c4 * 4 + 0][r] = v.x;
            As[c4 * 4 + 1][r] = v.y;
            As[c4 * 4 + 2][r] = v.z;
            As[c4 * 4 + 3][r] = v.w;
        }
        // Load B tile: 16 rows x 128 cols = 512 float4
#pragma unroll
        for (int it = 0; it < 2; it++) {
            int idx = tid + it * 256;
            int r   = idx >> 5;                  // 0..15
            int c4  = idx & 31;                  // 0..31
            float4 v = *(const float4*)(Bw + (size_t)(k0 + r) * DM + col0 + c4 * 4);
            *(float4*)&Bs[r][c4 * 4] = v;
        }
        __syncthreads();

#pragma unroll
        for (int k = 0; k < 16; k++) {
            float a[8], b[8];
#pragma unroll
            for (int i = 0; i < 8; i++) a[i] = As[k][ty * 8 + i];
#pragma unroll
            for (int j = 0; j < 8; j++) b[j] = Bs[k][tx * 8 + j];
#pragma unroll
            for (int i = 0; i < 8; i++)
#pragma unroll
                for (int j = 0; j < 8; j++) acc[i][j] += a[i] * b[j];
        }
        __syncthreads();
    }

    // Epilogue: scatter into [b, h, s, hd]
#pragma unroll
    for (int i = 0; i < 8; i++) {
        int r = row0 + ty * 8 + i;
        int b = r >> 11;            // r / 2048
        int s = r & 2047;
#pragma unroll
        for (int j = 0; j < 8; j++) {
            int c  = col0 + tx * 8 + j;
            int h  = c >> 6;
            int hd = c & 63;
            Out[(((size_t)(b * NH + h)) * SEQ + s) * HD + hd] = acc[i][j];
        }
    }
}

// Output projection: A = g_C [4096,1024], B = Wo, + bias, plain layout
__global__ __launch_bounds__(256) void out_gemm_kernel(
    const float* __restrict__ Wo,
    const float* __restrict__ bo,
    float* __restrict__ out)
{
    const int bn = blockIdx.x;
    const int bm = blockIdx.y;

    __shared__ float As[16][132];
    __shared__ float Bs[16][132];

    const int tid = threadIdx.x;
    const int tx = tid & 15;
    const int ty = tid >> 4;

    const int row0 = bm * 128;
    const int col0 = bn * 128;

    float acc[8][8];
#pragma unroll
    for (int i = 0; i < 8; i++)
#pragma unroll
        for (int j = 0; j < 8; j++) acc[i][j] = 0.f;

    for (int k0 = 0; k0 < DM; k0 += 16) {
#pragma unroll
        for (int it = 0; it < 2; it++) {
            int idx = tid + it * 256;
            int r   = idx >> 2;
            int c4  = idx & 3;
            float4 v = *(const float4*)(g_C + (size_t)(row0 + r) * DM + k0 + c4 * 4);
            As[c4 * 4 + 0][r] = v.x;
            As[c4 * 4 + 1][r] = v.y;
            As[c4 * 4 + 2][r] = v.z;
            As[c4 * 4 + 3][r] = v.w;
        }
#pragma unroll
        for (int it = 0; it < 2; it++) {
            int idx = tid + it * 256;
            int r   = idx >> 5;
            int c4  = idx & 31;
            float4 v = *(const float4*)(Wo + (size_t)(k0 + r) * DM + col0 + c4 * 4);
            *(float4*)&Bs[r][c4 * 4] = v;
        }
        __syncthreads();

#pragma unroll
        for (int k = 0; k < 16; k++) {
            float a[8], b[8];
#pragma unroll
            for (int i = 0; i < 8; i++) a[i] = As[k][ty * 8 + i];
#pragma unroll
            for (int j = 0; j < 8; j++) b[j] = Bs[k][tx * 8 + j];
#pragma unroll
            for (int i = 0; i < 8; i++)
#pragma unroll
                for (int j = 0; j < 8; j++) acc[i][j] += a[i] * b[j];
        }
        __syncthreads();
    }

#pragma unroll
    for (int i = 0; i < 8; i++) {
        int r = row0 + ty * 8 + i;
#pragma unroll
        for (int j = 0; j < 8; j++) {
            int c = col0 + tx * 8 + j;
            out[(size_t)r * DM + c] = acc[i][j] + bo[c];
        }
    }
}

// ---------------------------------------------------------------------------
// Sliding-window attention, flash style.
// Block = (bh, 64-query tile). 256 threads: thread = (q=tid/4, t=tid%4).
// Thread owns 16 keys (score phase) and 16 output dims (PV phase) per chunk.
// ---------------------------------------------------------------------------
#define ATTN_SMEM_FLOATS (3 * 64 * 65)

__global__ __launch_bounds__(256) void attn_kernel()
{
    extern __shared__ float sm[];
    float (*Qs)[65] = (float(*)[65])sm;                 // [64][65]
    float (*Ks)[65] = (float(*)[65])(sm + 64 * 65);     // also reused as P[q][j]
    float (*Vs)[65] = (float(*)[65])(sm + 2 * 64 * 65);

    const int qt = blockIdx.x;           // 0..31 query tile
    const int bh = blockIdx.y;           // 0..31 (b*16+h)
    const int b  = bh >> 4;
    const int h  = bh & 15;

    const int tid = threadIdx.x;
    const int q   = tid >> 2;            // 0..63 local query
    const int t   = tid & 3;             // 0..3  segment

    const float* __restrict__ Qg = g_Q + (size_t)bh * SEQ * HD;
    const float* __restrict__ Kg = g_K + (size_t)bh * SEQ * HD;
    const float* __restrict__ Vg = g_V + (size_t)bh * SEQ * HD;

    const int qs = qt * 64;
    const int qg = qs + q;

    // Load Q tile (64x64), float4
    for (int i = tid; i < 64 * 16; i += 256) {
        int r  = i >> 4;
        int c4 = i & 15;
        float4 v = *(const float4*)(Qg + (size_t)(qs + r) * HD + c4 * 4);
        Qs[r][c4 * 4 + 0] = v.x;
        Qs[r][c4 * 4 + 1] = v.y;
        Qs[r][c4 * 4 + 2] = v.z;
        Qs[r][c4 * 4 + 3] = v.w;
    }

    float m = -1e30f, l = 0.f;
    float o[16];
#pragma unroll
    for (int i = 0; i < 16; i++) o[i] = 0.f;

    int ks0 = qs - WIN; if (ks0 < 0) ks0 = 0;
    int ke  = qs + 64 + WIN; if (ke > SEQ) ke = SEQ;   // chunk-aligned

    for (int kb = ks0; kb < ke; kb += 64) {
        __syncthreads();   // previous PV done before overwriting Ks/Vs
        for (int i = tid; i < 64 * 16; i += 256) {
            int r  = i >> 4;
            int c4 = i & 15;
            float4 kv = *(const float4*)(Kg + (size_t)(kb + r) * HD + c4 * 4);
            Ks[r][c4 * 4 + 0] = kv.x;
            Ks[r][c4 * 4 + 1] = kv.y;
            Ks[r][c4 * 4 + 2] = kv.z;
            Ks[r][c4 * 4 + 3] = kv.w;
            float4 vv = *(const float4*)(Vg + (size_t)(kb + r) * HD + c4 * 4);
            Vs[r][c4 * 4 + 0] = vv.x;
            Vs[r][c4 * 4 + 1] = vv.y;
            Vs[r][c4 * 4 + 2] = vv.z;
            Vs[r][c4 * 4 + 3] = vv.w;
        }
        __syncthreads();

        // Scores for this thread's 16 keys
        float sc[16];
#pragma unroll
        for (int jj = 0; jj < 16; jj++) sc[jj] = 0.f;
#pragma unroll 8
        for (int d = 0; d < 64; d++) {
            float qv = Qs[q][d];
#pragma unroll
            for (int jj = 0; jj < 16; jj++)
                sc[jj] += qv * Ks[t * 16 + jj][d];
        }

        // Band mask + scale, chunk max
        float mc = -1e30f;
#pragma unroll
        for (int jj = 0; jj < 16; jj++) {
            int jgl = kb + t * 16 + jj;
            int dlt = jgl - qg;
            bool ok = (dlt <= WIN) && (dlt >= -WIN);
            sc[jj] = ok ? sc[jj] * 0.125f : -1e30f;
            mc = fmaxf(mc, sc[jj]);
        }
        mc = fmaxf(mc, __shfl_xor_sync(0xffffffffu, mc, 1));
        mc = fmaxf(mc, __shfl_xor_sync(0xffffffffu, mc, 2));

        float mn = fmaxf(m, mc);
        float f  = __expf(m - mn);
        float p[16];
        float ps = 0.f;
#pragma unroll
        for (int jj = 0; jj < 16; jj++) {
            p[jj] = __expf(sc[jj] - mn);
            ps += p[jj];
        }
        ps += __shfl_xor_sync(0xffffffffu, ps, 1);
        ps += __shfl_xor_sync(0xffffffffu, ps, 2);
        l = l * f + ps;
        m = mn;
#pragma unroll
        for (int i = 0; i < 16; i++) o[i] *= f;

        // Stash P into Ks (done reading K) as P[q][j]
        __syncthreads();
#pragma unroll
        for (int jj = 0; jj < 16; jj++)
            Ks[q][t * 16 + jj] = p[jj];
        __syncthreads();

        // O[dims t*16..t*16+15] += P[q][:] * V[:, dims]
#pragma unroll 4
        for (int j = 0; j < 64; j++) {
            float pv = Ks[q][j];
#pragma unroll
            for (int dd = 0; dd < 16; dd++)
                o[dd] += pv * Vs[j][t * 16 + dd];
        }
    }

    float inv = 1.f / l;
    size_t base = ((size_t)b * SEQ + qg) * DM + h * HD + t * 16;
#pragma unroll
    for (int dd = 0; dd < 16; dd++)
        g_C[base + dd] = o[dd] * inv;
}

// ---------------------------------------------------------------------------
extern "C" void kernel_launch(void* const* d_in, const int* in_sizes, int n_in,
                              void* d_out, int out_size)
{
    const float* x  = (const float*)d_in[0];
    const float* Wq = (const float*)d_in[1];
    const float* Wk = (const float*)d_in[2];
    const float* Wv = (const float*)d_in[3];
    const float* Wo = (const float*)d_in[4];
    const float* bo = (const float*)d_in[5];
    float* out = (float*)d_out;

    cudaFuncSetAttribute(attn_kernel, cudaFuncAttributeMaxDynamicSharedMemorySize,
                         ATTN_SMEM_FLOATS * (int)sizeof(float));

    qkv_gemm_kernel<<<dim3(DM / 128, (BATCH * SEQ) / 128, 3), 256>>>(x, Wq, Wk, Wv);
    attn_kernel<<<dim3(SEQ / 64, BATCH * NH), 256,
                  ATTN_SMEM_FLOATS * (int)sizeof(float)>>>();
    out_gemm_kernel<<<dim3(DM / 128, (BATCH * SEQ) / 128), 256>>>(Wo, bo, out);
}

// round 4
// speedup vs baseline: 3.0740x; 3.0740x over previous
#include <cuda_runtime.h>
#include <cuda_bf16.h>
#include <cstdint>

#define SEQ   2048
#define BATCH 2
#define NH    16
#define HD    64
#define DM    1024
#define WIN   256
#define MROWS (BATCH * SEQ)          // 4096

// ---------------------------------------------------------------------------
// Device scratch (allocation-guard-legal)
// ---------------------------------------------------------------------------
__device__ float g_Q[(size_t)MROWS * DM];
__device__ float g_K[(size_t)MROWS * DM];
__device__ float g_V[(size_t)MROWS * DM];
__device__ float g_C[(size_t)MROWS * DM];

__device__ __nv_bfloat16 g_xh[(size_t)MROWS * DM];
__device__ __nv_bfloat16 g_xl[(size_t)MROWS * DM];
__device__ __nv_bfloat16 g_Ch[(size_t)MROWS * DM];
__device__ __nv_bfloat16 g_Cl[(size_t)MROWS * DM];
__device__ __nv_bfloat16 g_Bh[(size_t)4 * DM * DM];   // W^T as [n][k]; q,k,v,o
__device__ __nv_bfloat16 g_Bl[(size_t)4 * DM * DM];

// ---------------------------------------------------------------------------
// PTX helpers (portable: sm_80+ tensor path, cp.async)
// ---------------------------------------------------------------------------
__device__ __forceinline__ uint32_t smem_u32(const void* p) {
    uint32_t a;
    asm("{ .reg .u64 t; cvta.to.shared.u64 t, %1; cvt.u32.u64 %0, t; }"
        : "=r"(a) : "l"(p));
    return a;
}

__device__ __forceinline__ void cpasync16(uint32_t dst, const void* src) {
    asm volatile("cp.async.cg.shared.global [%0], [%1], 16;"
                 :: "r"(dst), "l"(src));
}
#define CP_COMMIT() asm volatile("cp.async.commit_group;" ::: "memory")
#define CP_WAIT(n)  asm volatile("cp.async.wait_group %0;" :: "n"(n) : "memory")

__device__ __forceinline__ void ldsm4(uint32_t* r, uint32_t addr) {
    asm volatile("ldmatrix.sync.aligned.m8n8.x4.shared.b16 {%0,%1,%2,%3}, [%4];"
                 : "=r"(r[0]), "=r"(r[1]), "=r"(r[2]), "=r"(r[3]) : "r"(addr));
}

__device__ __forceinline__ void mma16816(float* c, const uint32_t* a, const uint32_t* b) {
    asm volatile(
        "mma.sync.aligned.m16n8k16.row.col.f32.bf16.bf16.f32 "
        "{%0,%1,%2,%3}, {%4,%5,%6,%7}, {%8,%9}, {%0,%1,%2,%3};"
        : "+f"(c[0]), "+f"(c[1]), "+f"(c[2]), "+f"(c[3])
        : "r"(a[0]), "r"(a[1]), "r"(a[2]), "r"(a[3]), "r"(b[0]), "r"(b[1]));
}

// ---------------------------------------------------------------------------
// Split fp32 -> bf16 hi/lo.  which==0: src = x (param) -> g_xh/g_xl
//                            which==1: src = g_C (device symbol) -> g_Ch/g_Cl
// ---------------------------------------------------------------------------
__global__ __launch_bounds__(256) void split_kernel(const float* __restrict__ xsrc, int which)
{
    const float* __restrict__ src = which ? (const float*)g_C : xsrc;
    __nv_bfloat16* __restrict__ dh = which ? g_Ch : g_xh;
    __nv_bfloat16* __restrict__ dl = which ? g_Cl : g_xl;
    int i = blockIdx.x * 256 + threadIdx.x;
    float4 v = ((const float4*)src)[i];
    __nv_bfloat16 h0 = __float2bfloat16(v.x);
    __nv_bfloat16 h1 = __float2bfloat16(v.y);
    __nv_bfloat16 h2 = __float2bfloat16(v.z);
    __nv_bfloat16 h3 = __float2bfloat16(v.w);
    ((__nv_bfloat162*)dh)[2 * i]     = __nv_bfloat162(h0, h1);
    ((__nv_bfloat162*)dh)[2 * i + 1] = __nv_bfloat162(h2, h3);
    ((__nv_bfloat162*)dl)[2 * i] = __nv_bfloat162(
        __float2bfloat16(v.x - __bfloat162float(h0)),
        __float2bfloat16(v.y - __bfloat162float(h1)));
    ((__nv_bfloat162*)dl)[2 * i + 1] = __nv_bfloat162(
        __float2bfloat16(v.z - __bfloat162float(h2)),
        __float2bfloat16(v.w - __bfloat162float(h3)));
}

// Split + transpose weights: g_B*[z][n][k] = W_z[k][n]
__global__ __launch_bounds__(256) void splitT_kernel(
    const float* __restrict__ w0, const float* __restrict__ w1,
    const float* __restrict__ w2, const float* __restrict__ w3)
{
    __shared__ float t[32][33];
    const int z = blockIdx.z;
    const float* __restrict__ W = (z == 0) ? w0 : (z == 1) ? w1 : (z == 2) ? w2 : w3;
    const int tx = threadIdx.x, ty = threadIdx.y;
    const int bx = blockIdx.x, by = blockIdx.y;
#pragma unroll
    for (int i = 0; i < 4; i++) {
        int k = by * 32 + ty + i * 8;
        int n = bx * 32 + tx;
        t[ty + i * 8][tx] = W[(size_t)k * DM + n];
    }
    __syncthreads();
    size_t base = (size_t)z * DM * DM;
#pragma unroll
    for (int i = 0; i < 4; i++) {
        int n = bx * 32 + ty + i * 8;
        int k = by * 32 + tx;
        float v = t[tx][ty + i * 8];
        __nv_bfloat16 h = __float2bfloat16(v);
        g_Bh[base + (size_t)n * DM + k] = h;
        g_Bl[base + (size_t)n * DM + k] = __float2bfloat16(v - __bfloat162float(h));
    }
}

// ---------------------------------------------------------------------------
// Split-bf16 HMMA GEMM: Out[4096,1024] = A[4096,1024] x W[1024,1024] (+bias)
// CTA tile 128x128, kTile 32, double-buffered cp.async. 8 warps of 64x32.
// Smem tile rows: 32 bf16 + 8 pad = 40 elems (80 B) -> conflict-free ldmatrix.
// mode 0: A = x(hi/lo), B = W{q,k,v} (z), out -> g_Q/g_K/g_V
// mode 1: A = C(hi/lo), B = Wo (slot 3), +bias -> outp
// ---------------------------------------------------------------------------
#define MMBUF   10240                      // 128 rows * 80 B
#define MMSTAGE (4 * MMBUF)                // Ah, Al, Bh, Bl
#define MM_SMEM (2 * MMSTAGE)              // 81920

__global__ __launch_bounds__(256, 1) void mm_kernel(
    const float* __restrict__ bias, float* __restrict__ outp, int mode)
{
    extern __shared__ char smc[];
    const uint32_t sm0 = smem_u32(smc);
    const int tid  = threadIdx.x;
    const int wid  = tid >> 5;
    const int lane = tid & 31;
    const int warpM = wid & 1;          // 2 x 64 rows
    const int warpN = wid >> 1;         // 4 x 32 cols
    const int row0 = blockIdx.y * 128;
    const int col0 = blockIdx.x * 128;
    const int z    = blockIdx.z;
    const int zz   = (mode == 0) ? z : 3;

    const __nv_bfloat16* __restrict__ Ah = (mode == 0) ? g_xh : g_Ch;
    const __nv_bfloat16* __restrict__ Al = (mode == 0) ? g_xl : g_Cl;
    const __nv_bfloat16* __restrict__ Bh = g_Bh + (size_t)zz * DM * DM;
    const __nv_bfloat16* __restrict__ Bl = g_Bl + (size_t)zz * DM * DM;

    float acc[4][4][4];
#pragma unroll
    for (int a = 0; a < 4; a++)
#pragma unroll
        for (int b = 0; b < 4; b++)
#pragma unroll
            for (int c = 0; c < 4; c++) acc[a][b][c] = 0.f;

    // ldmatrix addresses (per lane, fixed row patterns)
    const int a_r  = (lane & 7) + ((lane >> 3) & 1) * 8;   // row in m16
    const int a_kc = (lane >> 4) * 8;                      // k-half
    const int b_n  = (lane & 7) + (lane >> 4) * 8;         // n row in n16
    const int b_kc = ((lane >> 3) & 1) * 8;                // k-half

#define LOAD_STAGE(it_)                                                          \
    do {                                                                         \
        int k0_ = (it_) * 32;                                                    \
        uint32_t sb_ = sm0 + ((it_) & 1) * MMSTAGE;                              \
        _Pragma("unroll")                                                        \
        for (int i_ = 0; i_ < 2; i_++) {                                         \
            int idx_ = tid + i_ * 256;                                           \
            int r_ = idx_ >> 2, sg_ = idx_ & 3;                                  \
            uint32_t doff_ = r_ * 80 + sg_ * 16;                                 \
            cpasync16(sb_ + doff_,              Ah + (size_t)(row0 + r_) * DM + k0_ + sg_ * 8); \
            cpasync16(sb_ + MMBUF + doff_,      Al + (size_t)(row0 + r_) * DM + k0_ + sg_ * 8); \
            cpasync16(sb_ + 2 * MMBUF + doff_,  Bh + (size_t)(col0 + r_) * DM + k0_ + sg_ * 8); \
            cpasync16(sb_ + 3 * MMBUF + doff_,  Bl + (size_t)(col0 + r_) * DM + k0_ + sg_ * 8); \
        }                                                                        \
    } while (0)

    LOAD_STAGE(0);
    CP_COMMIT();

    for (int it = 0; it < 32; it++) {
        if (it + 1 < 32) {
            LOAD_STAGE(it + 1);
            CP_COMMIT();
            CP_WAIT(1);
        } else {
            CP_WAIT(0);
        }
        __syncthreads();

        uint32_t sb = sm0 + (it & 1) * MMSTAGE;
#pragma unroll
        for (int kk = 0; kk < 2; kk++) {
            uint32_t ah[4][4], al[4][4], bh[2][4], bl[2][4];
#pragma unroll
            for (int mb = 0; mb < 4; mb++) {
                int r = warpM * 64 + mb * 16 + a_r;
                uint32_t off = (uint32_t)(r * 80 + (kk * 16 + a_kc) * 2);
                ldsm4(ah[mb], sb + off);
                ldsm4(al[mb], sb + MMBUF + off);
            }
#pragma unroll
            for (int np = 0; np < 2; np++) {
                int n = warpN * 32 + np * 16 + b_n;
                uint32_t off = (uint32_t)(n * 80 + (kk * 16 + b_kc) * 2);
                ldsm4(bh[np], sb + 2 * MMBUF + off);
                ldsm4(bl[np], sb + 3 * MMBUF + off);
            }
#pragma unroll
            for (int mb = 0; mb < 4; mb++)
#pragma unroll
                for (int nb = 0; nb < 4; nb++) {
                    const uint32_t* bhf = &bh[nb >> 1][(nb & 1) * 2];
                    const uint32_t* blf = &bl[nb >> 1][(nb & 1) * 2];
                    mma16816(acc[mb][nb], ah[mb], bhf);
                    mma16816(acc[mb][nb], ah[mb], blf);
                    mma16816(acc[mb][nb], al[mb], bhf);
                }
        }
        __syncthreads();
    }

    // epilogue: direct fragment stores (float2 pairs)
    float* __restrict__ Out =
        (mode == 1) ? outp : ((z == 0) ? g_Q : (z == 1) ? g_K : g_V);
#pragma unroll
    for (int mb = 0; mb < 4; mb++) {
        int r = row0 + warpM * 64 + mb * 16 + (lane >> 2);
#pragma unroll
        for (int nb = 0; nb < 4; nb++) {
            int c = col0 + warpN * 32 + nb * 8 + (lane & 3) * 2;
            float2 v0 = make_float2(acc[mb][nb][0], acc[mb][nb][1]);
            float2 v1 = make_float2(acc[mb][nb][2], acc[mb][nb][3]);
            if (mode == 1) {
                v0.x += bias[c]; v0.y += bias[c + 1];
                v1.x += bias[c]; v1.y += bias[c + 1];
            }
            *(float2*)&Out[(size_t)r * DM + c]       = v0;
            *(float2*)&Out[(size_t)(r + 8) * DM + c] = v1;
        }
    }
#undef LOAD_STAGE
}

// ---------------------------------------------------------------------------
// Sliding-window attention (fp32, FFMA-bound layout)
// Q/K/V layout: [b*2048+s][1024], head at col h*64.
// Block: 256 threads = 8 warps; warp owns 8 queries x 64 keys of a 64-q tile.
// ---------------------------------------------------------------------------
#define AST 68
#define ATTN_SMEM (4 * 64 * AST * 4)

__global__ __launch_bounds__(256) void attn_kernel()
{
    extern __shared__ float smf[];
    float* Qs = smf;                 // [64][68]
    float* Ks = smf + 64 * AST;
    float* Vs = smf + 2 * 64 * AST;
    float* Ps = smf + 3 * 64 * AST;

    const int qt = blockIdx.x;
    const int bh = blockIdx.y;
    const int b  = bh >> 4;
    const int h  = bh & 15;

    const int tid  = threadIdx.x;
    const int w    = tid >> 5;
    const int lane = tid & 31;

    const float* __restrict__ Qg = g_Q + (size_t)b * SEQ * DM + h * HD;
    const float* __restrict__ Kg = g_K + (size_t)b * SEQ * DM + h * HD;
    const float* __restrict__ Vg = g_V + (size_t)b * SEQ * DM + h * HD;

    const int qs = qt * 64;

    for (int i = tid; i < 64 * 16; i += 256) {
        int r = i >> 4, c4 = i & 15;
        *(float4*)&Qs[r * AST + c4 * 4] =
            *(const float4*)(Qg + (size_t)(qs + r) * DM + c4 * 4);
    }

    float m[8], l[8];
    float4 o[8];
#pragma unroll
    for (int qi = 0; qi < 8; qi++) {
        m[qi] = -1e30f; l[qi] = 0.f;
        o[qi] = make_float4(0.f, 0.f, 0.f, 0.f);
    }

    int ks0 = qs - WIN; if (ks0 < 0) ks0 = 0;
    int ke  = qs + 64 + WIN; if (ke > SEQ) ke = SEQ;

    const int kh = (lane >> 4) << 5;       // 0 or 32: key half for PV
    const int dl = (lane & 15) * 4;        // d-slice for PV

    for (int kb = ks0; kb < ke; kb += 64) {
        __syncthreads();
        for (int i = tid; i < 64 * 16; i += 256) {
            int r = i >> 4, c4 = i & 15;
            *(float4*)&Ks[r * AST + c4 * 4] =
                *(const float4*)(Kg + (size_t)(kb + r) * DM + c4 * 4);
            *(float4*)&Vs[r * AST + c4 * 4] =
                *(const float4*)(Vg + (size_t)(kb + r) * DM + c4 * 4);
        }
        __syncthreads();

        float sc0[8], sc1[8];
#pragma unroll
        for (int qi = 0; qi < 8; qi++) { sc0[qi] = 0.f; sc1[qi] = 0.f; }
        const float* kp0 = Ks + lane * AST;
        const float* kp1 = Ks + (lane + 32) * AST;
#pragma unroll
        for (int d4 = 0; d4 < 64; d4 += 4) {
            float4 k0 = *(const float4*)(kp0 + d4);
            float4 k1 = *(const float4*)(kp1 + d4);
#pragma unroll
            for (int qi = 0; qi < 8; qi++) {
                float4 qv = *(const float4*)&Qs[(w * 8 + qi) * AST + d4];
                sc0[qi] += qv.x * k0.x + qv.y * k0.y + qv.z * k0.z + qv.w * k0.w;
                sc1[qi] += qv.x * k1.x + qv.y * k1.y + qv.z * k1.z + qv.w * k1.w;
            }
        }

        const int kg0 = kb + lane;
        const int kg1 = kb + lane + 32;
#pragma unroll
        for (int qi = 0; qi < 8; qi++) {
            int qg = qs + w * 8 + qi;
            float s0 = ((unsigned)(kg0 - qg + WIN) <= 2u * WIN) ? sc0[qi] * 0.125f : -1e30f;
            float s1 = ((unsigned)(kg1 - qg + WIN) <= 2u * WIN) ? sc1[qi] * 0.125f : -1e30f;
            float mc = fmaxf(s0, s1);
#pragma unroll
            for (int off = 16; off; off >>= 1)
                mc = fmaxf(mc, __shfl_xor_sync(0xffffffffu, mc, off));
            float mn = fmaxf(m[qi], mc);
            float f  = __expf(m[qi] - mn);
            float p0 = __expf(s0 - mn);
            float p1 = __expf(s1 - mn);
            float ps = p0 + p1;
#pragma unroll
            for (int off = 16; off; off >>= 1)
                ps += __shfl_xor_sync(0xffffffffu, ps, off);
            l[qi] = l[qi] * f + ps;
            m[qi] = mn;
            o[qi].x *= f; o[qi].y *= f; o[qi].z *= f; o[qi].w *= f;
            Ps[(w * 8 + qi) * AST + lane]      = p0;
            Ps[(w * 8 + qi) * AST + lane + 32] = p1;
        }
        __syncwarp();

#pragma unroll 4
        for (int kk = 0; kk < 32; kk++) {
            int k = kh + kk;
            float4 vv = *(const float4*)&Vs[k * AST + dl];
#pragma unroll
            for (int qi = 0; qi < 8; qi++) {
                float p = Ps[(w * 8 + qi) * AST + k];
                o[qi].x += p * vv.x; o[qi].y += p * vv.y;
                o[qi].z += p * vv.z; o[qi].w += p * vv.w;
            }
        }
    }

#pragma unroll
    for (int qi = 0; qi < 8; qi++) {
        o[qi].x += __shfl_xor_sync(0xffffffffu, o[qi].x, 16);
        o[qi].y += __shfl_xor_sync(0xffffffffu, o[qi].y, 16);
        o[qi].z += __shfl_xor_sync(0xffffffffu, o[qi].z, 16);
        o[qi].w += __shfl_xor_sync(0xffffffffu, o[qi].w, 16);
    }
    if (lane < 16) {
#pragma unroll
        for (int qi = 0; qi < 8; qi++) {
            float inv = 1.f / l[qi];
            float4 v = make_float4(o[qi].x * inv, o[qi].y * inv, o[qi].z * inv, o[qi].w * inv);
            int qg = qs + w * 8 + qi;
            *(float4*)&g_C[((size_t)b * SEQ + qg) * DM + h * HD + dl] = v;
        }
    }
}

// ---------------------------------------------------------------------------
extern "C" void kernel_launch(void* const* d_in, const int* in_sizes, int n_in,
                              void* d_out, int out_size)
{
    const float* x  = (const float*)d_in[0];
    const float* Wq = (const float*)d_in[1];
    const float* Wk = (const float*)d_in[2];
    const float* Wv = (const float*)d_in[3];
    const float* Wo = (const float*)d_in[4];
    const float* bo = (const float*)d_in[5];
    float* out = (float*)d_out;

    cudaFuncSetAttribute(mm_kernel, cudaFuncAttributeMaxDynamicSharedMemorySize, MM_SMEM);
    cudaFuncSetAttribute(attn_kernel, cudaFuncAttributeMaxDynamicSharedMemorySize, ATTN_SMEM);

    split_kernel<<<(MROWS * DM) / (4 * 256), 256>>>(x, 0);
    splitT_kernel<<<dim3(DM / 32, DM / 32, 4), dim3(32, 8)>>>(Wq, Wk, Wv, Wo);

    mm_kernel<<<dim3(DM / 128, MROWS / 128, 3), 256, MM_SMEM>>>(nullptr, nullptr, 0);

    attn_kernel<<<dim3(SEQ / 64, BATCH * NH), 256, ATTN_SMEM>>>();

    split_kernel<<<(MROWS * DM) / (4 * 256), 256>>>(nullptr, 1);
    mm_kernel<<<dim3(DM / 128, MROWS / 128, 1), 256, MM_SMEM>>>(bo, out, 1);
}

// round 5
// speedup vs baseline: 4.1900x; 1.3630x over previous
#include <cuda_runtime.h>
#include <cuda_bf16.h>
#include <cstdint>

#define SEQ   2048
#define BATCH 2
#define NH    16
#define HD    64
#define DM    1024
#define WIN   256
#define MROWS (BATCH * SEQ)          // 4096

// ---------------------------------------------------------------------------
// Device scratch (allocation-guard-legal). All activations kept as split bf16.
// ---------------------------------------------------------------------------
__device__ __nv_bfloat16 g_xh[(size_t)MROWS * DM];
__device__ __nv_bfloat16 g_xl[(size_t)MROWS * DM];
__device__ __nv_bfloat16 g_Ch[(size_t)MROWS * DM];
__device__ __nv_bfloat16 g_Cl[(size_t)MROWS * DM];
__device__ __nv_bfloat16 g_Qh[(size_t)MROWS * DM];
__device__ __nv_bfloat16 g_Ql[(size_t)MROWS * DM];
__device__ __nv_bfloat16 g_Kh[(size_t)MROWS * DM];
__device__ __nv_bfloat16 g_Kl[(size_t)MROWS * DM];
__device__ __nv_bfloat16 g_Vh[(size_t)MROWS * DM];
__device__ __nv_bfloat16 g_Vl[(size_t)MROWS * DM];
__device__ __nv_bfloat16 g_Bh[(size_t)4 * DM * DM];   // W^T as [n][k]; q,k,v,o
__device__ __nv_bfloat16 g_Bl[(size_t)4 * DM * DM];

// ---------------------------------------------------------------------------
// PTX helpers (portable: sm_80+ tensor path, cp.async)
// ---------------------------------------------------------------------------
__device__ __forceinline__ uint32_t smem_u32(const void* p) {
    uint32_t a;
    asm("{ .reg .u64 t; cvta.to.shared.u64 t, %1; cvt.u32.u64 %0, t; }"
        : "=r"(a) : "l"(p));
    return a;
}

__device__ __forceinline__ void cpasync16(uint32_t dst, const void* src) {
    asm volatile("cp.async.cg.shared.global [%0], [%1], 16;"
                 :: "r"(dst), "l"(src));
}
#define CP_COMMIT() asm volatile("cp.async.commit_group;" ::: "memory")
#define CP_WAIT(n)  asm volatile("cp.async.wait_group %0;" :: "n"(n) : "memory")

__device__ __forceinline__ void ldsm4(uint32_t* r, uint32_t addr) {
    asm volatile("ldmatrix.sync.aligned.m8n8.x4.shared.b16 {%0,%1,%2,%3}, [%4];"
                 : "=r"(r[0]), "=r"(r[1]), "=r"(r[2]), "=r"(r[3]) : "r"(addr));
}
__device__ __forceinline__ void ldsm4t(uint32_t* r, uint32_t addr) {
    asm volatile("ldmatrix.sync.aligned.m8n8.x4.trans.shared.b16 {%0,%1,%2,%3}, [%4];"
                 : "=r"(r[0]), "=r"(r[1]), "=r"(r[2]), "=r"(r[3]) : "r"(addr));
}

__device__ __forceinline__ void mma16816(float* c, const uint32_t* a, const uint32_t* b) {
    asm volatile(
        "mma.sync.aligned.m16n8k16.row.col.f32.bf16.bf16.f32 "
        "{%0,%1,%2,%3}, {%4,%5,%6,%7}, {%8,%9}, {%0,%1,%2,%3};"
        : "+f"(c[0]), "+f"(c[1]), "+f"(c[2]), "+f"(c[3])
        : "r"(a[0]), "r"(a[1]), "r"(a[2]), "r"(a[3]), "r"(b[0]), "r"(b[1]));
}

__device__ __forceinline__ uint32_t pkhi(float a, float b) {
    __nv_bfloat162 t = __floats2bfloat162_rn(a, b);
    return *reinterpret_cast<uint32_t*>(&t);
}
__device__ __forceinline__ uint32_t pklo(float a, float b, uint32_t hi) {
    __nv_bfloat162 h = *reinterpret_cast<__nv_bfloat162*>(&hi);
    return pkhi(a - __bfloat162float(h.x), b - __bfloat162float(h.y));
}

// ---------------------------------------------------------------------------
// Split fp32 x -> bf16 hi/lo
// ---------------------------------------------------------------------------
__global__ __launch_bounds__(256) void split_kernel(const float* __restrict__ src)
{
    int i = blockIdx.x * 256 + threadIdx.x;
    float4 v = ((const float4*)src)[i];
    uint32_t h01 = pkhi(v.x, v.y);
    uint32_t h23 = pkhi(v.z, v.w);
    ((uint32_t*)g_xh)[2 * i]     = h01;
    ((uint32_t*)g_xh)[2 * i + 1] = h23;
    ((uint32_t*)g_xl)[2 * i]     = pklo(v.x, v.y, h01);
    ((uint32_t*)g_xl)[2 * i + 1] = pklo(v.z, v.w, h23);
}

// Split + transpose weights: g_B*[z][n][k] = W_z[k][n]
__global__ __launch_bounds__(256) void splitT_kernel(
    const float* __restrict__ w0, const float* __restrict__ w1,
    const float* __restrict__ w2, const float* __restrict__ w3)
{
    __shared__ float t[32][33];
    const int z = blockIdx.z;
    const float* __restrict__ W = (z == 0) ? w0 : (z == 1) ? w1 : (z == 2) ? w2 : w3;
    const int tx = threadIdx.x, ty = threadIdx.y;
    const int bx = blockIdx.x, by = blockIdx.y;
#pragma unroll
    for (int i = 0; i < 4; i++) {
        int k = by * 32 + ty + i * 8;
        int n = bx * 32 + tx;
        t[ty + i * 8][tx] = W[(size_t)k * DM + n];
    }
    __syncthreads();
    size_t base = (size_t)z * DM * DM;
#pragma unroll
    for (int i = 0; i < 4; i++) {
        int n = bx * 32 + ty + i * 8;
        int k = by * 32 + tx;
        float v = t[tx][ty + i * 8];
        __nv_bfloat16 h = __float2bfloat16(v);
        g_Bh[base + (size_t)n * DM + k] = h;
        g_Bl[base + (size_t)n * DM + k] = __float2bfloat16(v - __bfloat162float(h));
    }
}

// ---------------------------------------------------------------------------
// Split-bf16 HMMA GEMM. CTA 128x128, kTile 32, double-buffered cp.async,
// 8 warps of 64x32. mode 0: x -> Qh/Ql, Kh/Kl, Vh/Vl (Q scaled 1/8).
// mode 1: C -> out fp32 (+bias).
// ---------------------------------------------------------------------------
#define MMBUF   10240                      // 128 rows * 80 B
#define MMSTAGE (4 * MMBUF)                // Ah, Al, Bh, Bl
#define MM_SMEM (2 * MMSTAGE)              // 81920

__global__ __launch_bounds__(256, 1) void mm_kernel(
    const float* __restrict__ bias, float* __restrict__ outp, int mode)
{
    extern __shared__ char smc[];
    const uint32_t sm0 = smem_u32(smc);
    const int tid  = threadIdx.x;
    const int lane = tid & 31;
    const int wid  = tid >> 5;
    const int warpM = wid & 1;
    const int warpN = wid >> 1;
    const int row0 = blockIdx.y * 128;
    const int col0 = blockIdx.x * 128;
    const int z    = blockIdx.z;
    const int zz   = (mode == 0) ? z : 3;

    const __nv_bfloat16* __restrict__ Ah = (mode == 0) ? g_xh : g_Ch;
    const __nv_bfloat16* __restrict__ Al = (mode == 0) ? g_xl : g_Cl;
    const __nv_bfloat16* __restrict__ Bh = g_Bh + (size_t)zz * DM * DM;
    const __nv_bfloat16* __restrict__ Bl = g_Bl + (size_t)zz * DM * DM;

    float acc[4][4][4];
#pragma unroll
    for (int a = 0; a < 4; a++)
#pragma unroll
        for (int b = 0; b < 4; b++)
#pragma unroll
            for (int c = 0; c < 4; c++) acc[a][b][c] = 0.f;

    const int a_r  = (lane & 7) + ((lane >> 3) & 1) * 8;
    const int a_kc = (lane >> 4) * 8;
    const int b_n  = (lane & 7) + (lane >> 4) * 8;
    const int b_kc = ((lane >> 3) & 1) * 8;

#define LOAD_STAGE(it_)                                                          \
    do {                                                                         \
        int k0_ = (it_) * 32;                                                    \
        uint32_t sb_ = sm0 + ((it_) & 1) * MMSTAGE;                              \
        _Pragma("unroll")                                                        \
        for (int i_ = 0; i_ < 2; i_++) {                                         \
            int idx_ = tid + i_ * 256;                                           \
            int r_ = idx_ >> 2, sg_ = idx_ & 3;                                  \
            uint32_t doff_ = r_ * 80 + sg_ * 16;                                 \
            cpasync16(sb_ + doff_,              Ah + (size_t)(row0 + r_) * DM + k0_ + sg_ * 8); \
            cpasync16(sb_ + MMBUF + doff_,      Al + (size_t)(row0 + r_) * DM + k0_ + sg_ * 8); \
            cpasync16(sb_ + 2 * MMBUF + doff_,  Bh + (size_t)(col0 + r_) * DM + k0_ + sg_ * 8); \
            cpasync16(sb_ + 3 * MMBUF + doff_,  Bl + (size_t)(col0 + r_) * DM + k0_ + sg_ * 8); \
        }                                                                        \
    } while (0)

    LOAD_STAGE(0);
    CP_COMMIT();

    for (int it = 0; it < 32; it++) {
        if (it + 1 < 32) {
            LOAD_STAGE(it + 1);
            CP_COMMIT();
            CP_WAIT(1);
        } else {
            CP_WAIT(0);
        }
        __syncthreads();

        uint32_t sb = sm0 + (it & 1) * MMSTAGE;
#pragma unroll
        for (int kk = 0; kk < 2; kk++) {
            uint32_t ah[4][4], al[4][4], bh[2][4], bl[2][4];
#pragma unroll
            for (int mb = 0; mb < 4; mb++) {
                int r = warpM * 64 + mb * 16 + a_r;
                uint32_t off = (uint32_t)(r * 80 + (kk * 16 + a_kc) * 2);
                ldsm4(ah[mb], sb + off);
                ldsm4(al[mb], sb + MMBUF + off);
            }
#pragma unroll
            for (int np = 0; np < 2; np++) {
                int n = warpN * 32 + np * 16 + b_n;
                uint32_t off = (uint32_t)(n * 80 + (kk * 16 + b_kc) * 2);
                ldsm4(bh[np], sb + 2 * MMBUF + off);
                ldsm4(bl[np], sb + 3 * MMBUF + off);
            }
#pragma unroll
            for (int mb = 0; mb < 4; mb++)
#pragma unroll
                for (int nb = 0; nb < 4; nb++) {
                    const uint32_t* bhf = &bh[nb >> 1][(nb & 1) * 2];
                    const uint32_t* blf = &bl[nb >> 1][(nb & 1) * 2];
                    mma16816(acc[mb][nb], ah[mb], bhf);
                    mma16816(acc[mb][nb], ah[mb], blf);
                    mma16816(acc[mb][nb], al[mb], bhf);
                }
        }
        __syncthreads();
    }

    if (mode == 0) {
        __nv_bfloat16* __restrict__ Oh = (z == 0) ? g_Qh : (z == 1) ? g_Kh : g_Vh;
        __nv_bfloat16* __restrict__ Ol = (z == 0) ? g_Ql : (z == 1) ? g_Kl : g_Vl;
        const float sc = (z == 0) ? 0.125f : 1.0f;
#pragma unroll
        for (int mb = 0; mb < 4; mb++) {
            int r = row0 + warpM * 64 + mb * 16 + (lane >> 2);
#pragma unroll
            for (int nb = 0; nb < 4; nb++) {
                int c = col0 + warpN * 32 + nb * 8 + (lane & 3) * 2;
                float v0 = acc[mb][nb][0] * sc, v1 = acc[mb][nb][1] * sc;
                float v2 = acc[mb][nb][2] * sc, v3 = acc[mb][nb][3] * sc;
                uint32_t h01 = pkhi(v0, v1);
                uint32_t h23 = pkhi(v2, v3);
                *(uint32_t*)&Oh[(size_t)r * DM + c]       = h01;
                *(uint32_t*)&Ol[(size_t)r * DM + c]       = pklo(v0, v1, h01);
                *(uint32_t*)&Oh[(size_t)(r + 8) * DM + c] = h23;
                *(uint32_t*)&Ol[(size_t)(r + 8) * DM + c] = pklo(v2, v3, h23);
            }
        }
    } else {
#pragma unroll
        for (int mb = 0; mb < 4; mb++) {
            int r = row0 + warpM * 64 + mb * 16 + (lane >> 2);
#pragma unroll
            for (int nb = 0; nb < 4; nb++) {
                int c = col0 + warpN * 32 + nb * 8 + (lane & 3) * 2;
                float2 v0 = make_float2(acc[mb][nb][0] + bias[c], acc[mb][nb][1] + bias[c + 1]);
                float2 v1 = make_float2(acc[mb][nb][2] + bias[c], acc[mb][nb][3] + bias[c + 1]);
                *(float2*)&outp[(size_t)r * DM + c]       = v0;
                *(float2*)&outp[(size_t)(r + 8) * DM + c] = v1;
            }
        }
    }
#undef LOAD_STAGE
}

// ---------------------------------------------------------------------------
// HMMA flash attention, split-bf16 (3-term) for QK^T and PV.
// Block 128 thr = 4 warps, 64-query tile; warp w owns rows w*16..w*16+15.
// Chunks of 64 keys. Writes Ch/Cl (split bf16) for the output projection.
// ---------------------------------------------------------------------------
#define KST 72                                   // bf16 elems per smem row (144 B)
#define ATILE (64 * KST)                         // one 64x64 tile (elems)
#define ATTN_SMEM (6 * ATILE * 2)                // 55296 B

__global__ __launch_bounds__(128) void attn_kernel()
{
    extern __shared__ __nv_bfloat16 smb[];
    __nv_bfloat16* Qhs = smb;
    __nv_bfloat16* Qls = smb + ATILE;
    __nv_bfloat16* Khs = smb + 2 * ATILE;
    __nv_bfloat16* Kls = smb + 3 * ATILE;
    __nv_bfloat16* Vhs = smb + 4 * ATILE;
    __nv_bfloat16* Vls = smb + 5 * ATILE;

    const int qt = blockIdx.x;
    const int bh = blockIdx.y;
    const int b  = bh >> 4;
    const int h  = bh & 15;
    const int tid  = threadIdx.x;
    const int w    = tid >> 5;
    const int lane = tid & 31;
    const int qs = qt * 64;

    const size_t hoff = (size_t)b * SEQ * DM + h * HD;
    const __nv_bfloat16* __restrict__ Qgh = g_Qh + hoff;
    const __nv_bfloat16* __restrict__ Qgl = g_Ql + hoff;
    const __nv_bfloat16* __restrict__ Kgh = g_Kh + hoff;
    const __nv_bfloat16* __restrict__ Kgl = g_Kl + hoff;
    const __nv_bfloat16* __restrict__ Vgh = g_Vh + hoff;
    const __nv_bfloat16* __restrict__ Vgl = g_Vl + hoff;

    // load Q tile (64 rows x 64 bf16, 8 uint4 per row)
    for (int i = tid; i < 64 * 8; i += 128) {
        int r = i >> 3, c = i & 7;
        *(uint4*)&Qhs[r * KST + c * 8] = *(const uint4*)(Qgh + (size_t)(qs + r) * DM + c * 8);
        *(uint4*)&Qls[r * KST + c * 8] = *(const uint4*)(Qgl + (size_t)(qs + r) * DM + c * 8);
    }
    __syncthreads();

    // Q A-fragments (persist across chunks)
    const int a_r  = (lane & 7) + ((lane >> 3) & 1) * 8;
    const int a_kc = (lane >> 4) * 8;
    uint32_t qa_h[4][4], qa_l[4][4];
#pragma unroll
    for (int kk = 0; kk < 4; kk++) {
        uint32_t off = (uint32_t)((w * 16 + a_r) * KST + kk * 16 + a_kc) * 2;
        ldsm4(qa_h[kk], smem_u32(Qhs) + off);
        ldsm4(qa_l[kk], smem_u32(Qls) + off);
    }

    float O[8][4];
#pragma unroll
    for (int t = 0; t < 8; t++)
#pragma unroll
        for (int e = 0; e < 4; e++) O[t][e] = 0.f;
    float m0 = -1e30f, m1 = -1e30f, l0 = 0.f, l1 = 0.f;

    const int b_n  = (lane & 7) + (lane >> 4) * 8;
    const int b_kc = ((lane >> 3) & 1) * 8;
    const int v_r  = lane & 15;
    const int v_c  = (lane >> 4) * 8;
    const int q0 = qs + w * 16 + (lane >> 2);
    const int q1 = q0 + 8;

    int ks0 = qs - WIN; if (ks0 < 0) ks0 = 0;
    int ke  = qs + 64 + WIN; if (ke > SEQ) ke = SEQ;

    for (int kb = ks0; kb < ke; kb += 64) {
        __syncthreads();
        for (int i = tid; i < 64 * 8; i += 128) {
            int r = i >> 3, c = i & 7;
            size_t g = (size_t)(kb + r) * DM + c * 8;
            *(uint4*)&Khs[r * KST + c * 8] = *(const uint4*)(Kgh + g);
            *(uint4*)&Kls[r * KST + c * 8] = *(const uint4*)(Kgl + g);
            *(uint4*)&Vhs[r * KST + c * 8] = *(const uint4*)(Vgh + g);
            *(uint4*)&Vls[r * KST + c * 8] = *(const uint4*)(Vgl + g);
        }
        __syncthreads();

        // ---- scores S[64q x 64k] per warp rows
        float S[8][4];
#pragma unroll
        for (int t = 0; t < 8; t++)
#pragma unroll
            for (int e = 0; e < 4; e++) S[t][e] = 0.f;

#pragma unroll
        for (int kk = 0; kk < 4; kk++) {
#pragma unroll
            for (int nt = 0; nt < 4; nt++) {
                uint32_t kh[4], kl[4];
                uint32_t off = (uint32_t)((nt * 16 + b_n) * KST + kk * 16 + b_kc) * 2;
                ldsm4(kh, smem_u32(Khs) + off);
                ldsm4(kl, smem_u32(Kls) + off);
#pragma unroll
                for (int half = 0; half < 2; half++) {
                    float* s = S[nt * 2 + half];
                    mma16816(s, qa_h[kk], &kh[half * 2]);
                    mma16816(s, qa_h[kk], &kl[half * 2]);
                    mma16816(s, qa_l[kk], &kh[half * 2]);
                }
            }
        }

        // ---- mask + online softmax (register frags, quad reduction)
        const int kc = kb + 2 * (lane & 3);
        float mx0 = -1e30f, mx1 = -1e30f;
#pragma unroll
        for (int j = 0; j < 8; j++) {
            int d0 = kc + j * 8 - q0 + WIN;       // row q0, col pair
            int d2 = d0 + 8;                      // row q1 is q0+8 -> delta -8
            S[j][0] = ((unsigned)d0 <= 2u * WIN)       ? S[j][0] : -1e30f;
            S[j][1] = ((unsigned)(d0 + 1) <= 2u * WIN) ? S[j][1] : -1e30f;
            S[j][2] = ((unsigned)(d0 - 8) <= 2u * WIN) ? S[j][2] : -1e30f;
            S[j][3] = ((unsigned)(d0 - 7) <= 2u * WIN) ? S[j][3] : -1e30f;
            (void)d2;
            mx0 = fmaxf(mx0, fmaxf(S[j][0], S[j][1]));
            mx1 = fmaxf(mx1, fmaxf(S[j][2], S[j][3]));
        }
        mx0 = fmaxf(mx0, __shfl_xor_sync(0xffffffffu, mx0, 1));
        mx0 = fmaxf(mx0, __shfl_xor_sync(0xffffffffu, mx0, 2));
        mx1 = fmaxf(mx1, __shfl_xor_sync(0xffffffffu, mx1, 1));
        mx1 = fmaxf(mx1, __shfl_xor_sync(0xffffffffu, mx1, 2));

        float mn0 = fmaxf(m0, mx0), mn1 = fmaxf(m1, mx1);
        float f0 = __expf(m0 - mn0), f1 = __expf(m1 - mn1);
        float s0 = 0.f, s1 = 0.f;
#pragma unroll
        for (int j = 0; j < 8; j++) {
            S[j][0] = __expf(S[j][0] - mn0);
            S[j][1] = __expf(S[j][1] - mn0);
            S[j][2] = __expf(S[j][2] - mn1);
            S[j][3] = __expf(S[j][3] - mn1);
            s0 += S[j][0] + S[j][1];
            s1 += S[j][2] + S[j][3];
        }
        s0 += __shfl_xor_sync(0xffffffffu, s0, 1);
        s0 += __shfl_xor_sync(0xffffffffu, s0, 2);
        s1 += __shfl_xor_sync(0xffffffffu, s1, 1);
        s1 += __shfl_xor_sync(0xffffffffu, s1, 2);
        l0 = l0 * f0 + s0;  m0 = mn0;
        l1 = l1 * f1 + s1;  m1 = mn1;
#pragma unroll
        for (int t = 0; t < 8; t++) {
            O[t][0] *= f0; O[t][1] *= f0;
            O[t][2] *= f1; O[t][3] *= f1;
        }

        // ---- PV: P frags packed from S on the fly; V via ldmatrix.trans
#pragma unroll
        for (int kk = 0; kk < 4; kk++) {
            uint32_t pa_h[4], pa_l[4];
            const float* sj0 = S[2 * kk];
            const float* sj1 = S[2 * kk + 1];
            pa_h[0] = pkhi(sj0[0], sj0[1]);  pa_l[0] = pklo(sj0[0], sj0[1], pa_h[0]);
            pa_h[1] = pkhi(sj0[2], sj0[3]);  pa_l[1] = pklo(sj0[2], sj0[3], pa_h[1]);
            pa_h[2] = pkhi(sj1[0], sj1[1]);  pa_l[2] = pklo(sj1[0], sj1[1], pa_h[2]);
            pa_h[3] = pkhi(sj1[2], sj1[3]);  pa_l[3] = pklo(sj1[2], sj1[3], pa_h[3]);
#pragma unroll
            for (int nt = 0; nt < 4; nt++) {
                uint32_t vh[4], vl[4];
                uint32_t off = (uint32_t)((kk * 16 + v_r) * KST + nt * 16 + v_c) * 2;
                ldsm4t(vh, smem_u32(Vhs) + off);
                ldsm4t(vl, smem_u32(Vls) + off);
#pragma unroll
                for (int half = 0; half < 2; half++) {
                    float* o = O[nt * 2 + half];
                    mma16816(o, pa_h, &vh[half * 2]);
                    mma16816(o, pa_l, &vh[half * 2]);
                    mma16816(o, pa_h, &vl[half * 2]);
                }
            }
        }
    }

    // ---- epilogue: normalize, split, store Ch/Cl
    float inv0 = 1.f / l0, inv1 = 1.f / l1;
#pragma unroll
    for (int t = 0; t < 8; t++) {
        int c = h * HD + t * 8 + 2 * (lane & 3);
        float v0 = O[t][0] * inv0, v1 = O[t][1] * inv0;
        float v2 = O[t][2] * inv1, v3 = O[t][3] * inv1;
        size_t r0o = ((size_t)b * SEQ + q0) * DM + c;
        size_t r1o = ((size_t)b * SEQ + q1) * DM + c;
        uint32_t h01 = pkhi(v0, v1);
        uint32_t h23 = pkhi(v2, v3);
        *(uint32_t*)&g_Ch[r0o] = h01;
        *(uint32_t*)&g_Cl[r0o] = pklo(v0, v1, h01);
        *(uint32_t*)&g_Ch[r1o] = h23;
        *(uint32_t*)&g_Cl[r1o] = pklo(v2, v3, h23);
    }
}

// ---------------------------------------------------------------------------
extern "C" void kernel_launch(void* const* d_in, const int* in_sizes, int n_in,
                              void* d_out, int out_size)
{
    const float* x  = (const float*)d_in[0];
    const float* Wq = (const float*)d_in[1];
    const float* Wk = (const float*)d_in[2];
    const float* Wv = (const float*)d_in[3];
    const float* Wo = (const float*)d_in[4];
    const float* bo = (const float*)d_in[5];
    float* out = (float*)d_out;

    cudaFuncSetAttribute(mm_kernel, cudaFuncAttributeMaxDynamicSharedMemorySize, MM_SMEM);
    cudaFuncSetAttribute(attn_kernel, cudaFuncAttributeMaxDynamicSharedMemorySize, ATTN_SMEM);

    split_kernel<<<(MROWS * DM) / (4 * 256), 256>>>(x);
    splitT_kernel<<<dim3(DM / 32, DM / 32, 4), dim3(32, 8)>>>(Wq, Wk, Wv, Wo);

    mm_kernel<<<dim3(DM / 128, MROWS / 128, 3), 256, MM_SMEM>>>(nullptr, nullptr, 0);

    attn_kernel<<<dim3(SEQ / 64, BATCH * NH), 128, ATTN_SMEM>>>();

    mm_kernel<<<dim3(DM / 128, MROWS / 128, 1), 256, MM_SMEM>>>(bo, out, 1);
}